// round 12
// baseline (speedup 1.0000x reference)
#include <cuda_runtime.h>
#include <cuda_bf16.h>

// Sparsemax rows of 2048 fp32 — persistent CTA-per-row, register prefetch.
// Geometry: 512 threads/CTA, 4 elements (1 float4) per thread, 4 CTAs/SM
// -> 100% occupancy (vs 75% at 256x8). Algorithm identical to the best
// kernel: gather candidates > THETA (static, ~25/row) via max-prefiltered
// shared atomics; warp 0 solves Michelot; tau >= THETA self-certifies
// exactness (KKT: all discarded <= THETA <= tau); coalesced streaming store.
// Full-block Michelot fallback keeps general correctness.

#define ROWLEN  2048
#define THREADS 512
#define VPT     (ROWLEN / THREADS)   // 4
#define NWARP   (THREADS / 32)       // 16
#define F4PROW  (ROWLEN / 4)         // 512 == THREADS
#define CAP     64
#define THETA   2.25f
#define NEG_INF (-3.0e38f)
#define FULLM   0xffffffffu
#define OCC     4
#define GRID_CTAS (148 * OCC)

__global__ __launch_bounds__(THREADS, OCC)
void sparsemax_kernel(const float* __restrict__ z, float* __restrict__ out, int rows) {
    const float4* __restrict__ z4   = reinterpret_cast<const float4*>(z);
    float4* __restrict__       out4 = reinterpret_cast<float4*>(out);
    const int tid  = threadIdx.x;
    const int lane = tid & 31;
    const int wid  = tid >> 5;
    const long long stride = gridDim.x;

    __shared__ float s_cand[CAP];
    __shared__ int   s_n;
    __shared__ float s_tau;
    __shared__ int   s_ok;
    __shared__ float s_red[NWARP];
    __shared__ float s_cnt[NWARP];

    long long r = blockIdx.x;
    if (r >= rows) return;

    if (tid == 0) s_n = 0;

    // prime the pipeline: this thread's single float4 of the first row
    float4 a = __ldcs(&z4[r * F4PROW + tid]);
    __syncthreads();   // s_n init visible

    #pragma unroll 1
    while (true) {
        const long long rn = r + stride;
        const float4 q = a;

        // ---- gather candidates > THETA (3-fmax prefilter, rare atomics) ----
        float m = fmaxf(fmaxf(q.x, q.y), fmaxf(q.z, q.w));
        if (m > THETA) {
            if (q.x > THETA) { int ix = atomicAdd(&s_n, 1); if (ix < CAP) s_cand[ix] = q.x; }
            if (q.y > THETA) { int ix = atomicAdd(&s_n, 1); if (ix < CAP) s_cand[ix] = q.y; }
            if (q.z > THETA) { int ix = atomicAdd(&s_n, 1); if (ix < CAP) s_cand[ix] = q.z; }
            if (q.w > THETA) { int ix = atomicAdd(&s_n, 1); if (ix < CAP) s_cand[ix] = q.w; }
        }

        // ---- prefetch next row before the barriers (hides DRAM latency) ----
        if (rn < rows) a = __ldcs(&z4[rn * F4PROW + tid]);
        __syncthreads();   // gather complete

        // ---- warp 0: Michelot on candidate set; certify tau >= THETA ----
        if (wid == 0) {
            const int n = s_n;
            float c0 = (lane < n)      ? s_cand[lane]      : NEG_INF;
            float c1 = (lane + 32 < n) ? s_cand[lane + 32] : NEG_INF;
            float s0 = (c0 > NEG_INF ? c0 : 0.0f) + (c1 > NEG_INF ? c1 : 0.0f);
            #pragma unroll
            for (int o = 16; o > 0; o >>= 1) s0 += __shfl_xor_sync(FULLM, s0, o);
            float tau = (s0 - 1.0f) / (float)(n > 0 ? (n <= CAP ? n : CAP) : 1);
            int prev = -1;
            #pragma unroll 1
            for (int it = 0; it < 32; it++) {
                float s = 0.0f, cnt = 0.0f;
                bool a0 = c0 > tau, a1 = c1 > tau;
                s   += a0 ? c0 : 0.0f;    cnt += a0 ? 1.0f : 0.0f;
                s   += a1 ? c1 : 0.0f;    cnt += a1 ? 1.0f : 0.0f;
                #pragma unroll
                for (int o = 16; o > 0; o >>= 1) {
                    s   += __shfl_xor_sync(FULLM, s, o);
                    cnt += __shfl_xor_sync(FULLM, cnt, o);
                }
                if (cnt == 0.0f) break;
                tau = (s - 1.0f) / cnt;
                int k = (int)cnt;
                if (k == prev) break;
                prev = k;
            }
            if (lane == 0) {
                s_tau = tau;
                s_ok  = (n > 0 && n <= CAP && tau >= THETA) ? 1 : 0;
                s_n   = 0;   // next gather begins only after the next barrier
            }
        }
        __syncthreads();   // s_tau/s_ok visible, s_n reset

        if (s_ok) {
            // ---- fast path: coalesced streaming projection store ----
            const float tau = s_tau;
            float4 o;
            o.x = fmaxf(q.x - tau, 0.0f);
            o.y = fmaxf(q.y - tau, 0.0f);
            o.z = fmaxf(q.z - tau, 0.0f);
            o.w = fmaxf(q.w - tau, 0.0f);
            __stcs(&out4[r * F4PROW + tid], o);
        } else {
            // ---- fallback: full-block Michelot over register-resident row ----
            float tau;
            {
                float s = (q.x + q.y) + (q.z + q.w);
                #pragma unroll
                for (int o = 16; o > 0; o >>= 1) s += __shfl_xor_sync(FULLM, s, o);
                if (lane == 0) s_red[wid] = s;
                __syncthreads();
                if (tid == 0) {
                    float tot = 0.0f;
                    #pragma unroll
                    for (int w = 0; w < NWARP; w++) tot += s_red[w];
                    s_tau = (tot - 1.0f) * (1.0f / (float)ROWLEN);
                }
                __syncthreads();
                tau = s_tau;
            }
            int k_prev = ROWLEN;
            #pragma unroll 1
            for (int it = 0; it < 64; it++) {
                float s = 0.0f, cf = 0.0f;
                if (q.x > tau) { s += q.x; cf += 1.0f; }
                if (q.y > tau) { s += q.y; cf += 1.0f; }
                if (q.z > tau) { s += q.z; cf += 1.0f; }
                if (q.w > tau) { s += q.w; cf += 1.0f; }
                #pragma unroll
                for (int o = 16; o > 0; o >>= 1) {
                    s  += __shfl_xor_sync(FULLM, s, o);
                    cf += __shfl_xor_sync(FULLM, cf, o);
                }
                if (lane == 0) { s_red[wid] = s; s_cnt[wid] = cf; }
                __syncthreads();
                if (tid == 0) {
                    float ts = 0.0f, tc = 0.0f;
                    #pragma unroll
                    for (int w = 0; w < NWARP; w++) { ts += s_red[w]; tc += s_cnt[w]; }
                    s_tau = (ts - 1.0f) / tc;
                    s_cnt[0] = tc;
                }
                __syncthreads();
                tau = s_tau;
                int k = (int)s_cnt[0];
                __syncthreads();
                if (k == k_prev) break;
                k_prev = k;
            }
            float4 o;
            o.x = fmaxf(q.x - tau, 0.0f);
            o.y = fmaxf(q.y - tau, 0.0f);
            o.z = fmaxf(q.z - tau, 0.0f);
            o.w = fmaxf(q.w - tau, 0.0f);
            out4[r * F4PROW + tid] = o;
        }

        if (rn >= rows) break;
        r = rn;
    }
}

extern "C" void kernel_launch(void* const* d_in, const int* in_sizes, int n_in,
                              void* d_out, int out_size) {
    const float* z = (const float*)d_in[0];
    float* out = (float*)d_out;
    int rows = in_sizes[0] / ROWLEN;
    int grid = GRID_CTAS < rows ? GRID_CTAS : rows;
    sparsemax_kernel<<<grid, THREADS>>>(z, out, rows);
}

// round 13
// speedup vs baseline: 1.1019x; 1.1019x over previous
#include <cuda_runtime.h>
#include <cuda_bf16.h>

// Sparsemax rows of 2048 fp32 — persistent CTA-per-row, register prefetch.
// Geometry tuned for memory-level parallelism: 128 threads/CTA, 16 elements
// (4 float4) per thread + 4-float4 prefetch of the next row, 9 CTAs/SM.
// In-flight loads/SM = 9*128*4 float4 (1.5x the previous best), barriers
// couple only 4 warps, and 9 CTAs/SM stagger the warp-0 solve windows.
// Algorithm (proven): static THETA gather via max-prefiltered shared atomics;
// warp 0 Michelot on candidates; tau >= THETA self-certifies exactness (KKT);
// coalesced streaming store; full-block Michelot fallback for correctness.

#define ROWLEN  2048
#define THREADS 128
#define NF4     4                    // float4 per thread
#define VPT     (NF4 * 4)            // 16
#define NWARP   (THREADS / 32)       // 4
#define F4PROW  (ROWLEN / 4)         // 512
#define CAP     64
#define THETA   2.25f
#define NEG_INF (-3.0e38f)
#define FULLM   0xffffffffu
#define OCC     9
#define GRID_CTAS (148 * OCC)

__global__ __launch_bounds__(THREADS, OCC)
void sparsemax_kernel(const float* __restrict__ z, float* __restrict__ out, int rows) {
    const float4* __restrict__ z4   = reinterpret_cast<const float4*>(z);
    float4* __restrict__       out4 = reinterpret_cast<float4*>(out);
    const int tid  = threadIdx.x;
    const int lane = tid & 31;
    const int wid  = tid >> 5;
    const long long stride = gridDim.x;

    __shared__ float s_cand[CAP];
    __shared__ int   s_n;
    __shared__ float s_tau;
    __shared__ int   s_ok;
    __shared__ float s_red[NWARP];
    __shared__ float s_cnt[NWARP];

    long long r = blockIdx.x;
    if (r >= rows) return;

    if (tid == 0) s_n = 0;

    // prime: this thread's 4 float4 slices of the first row (MLP = 4)
    float4 cur[NF4];
    #pragma unroll
    for (int j = 0; j < NF4; j++)
        cur[j] = __ldcs(&z4[r * F4PROW + tid + THREADS * j]);
    __syncthreads();   // s_n init visible

    #pragma unroll 1
    while (true) {
        const long long rn = r + stride;

        // ---- gather candidates > THETA (per-quad max prefilter, rare atomics) ----
        #pragma unroll
        for (int j = 0; j < NF4; j++) {
            const float4 q = cur[j];
            float m = fmaxf(fmaxf(q.x, q.y), fmaxf(q.z, q.w));
            if (m > THETA) {
                if (q.x > THETA) { int ix = atomicAdd(&s_n, 1); if (ix < CAP) s_cand[ix] = q.x; }
                if (q.y > THETA) { int ix = atomicAdd(&s_n, 1); if (ix < CAP) s_cand[ix] = q.y; }
                if (q.z > THETA) { int ix = atomicAdd(&s_n, 1); if (ix < CAP) s_cand[ix] = q.z; }
                if (q.w > THETA) { int ix = atomicAdd(&s_n, 1); if (ix < CAP) s_cand[ix] = q.w; }
            }
        }

        // ---- prefetch next row (4 independent LDG.128 per thread) ----
        float4 nxt[NF4];
        if (rn < rows) {
            #pragma unroll
            for (int j = 0; j < NF4; j++)
                nxt[j] = __ldcs(&z4[rn * F4PROW + tid + THREADS * j]);
        }
        __syncthreads();   // gather complete

        // ---- warp 0: Michelot on candidate set; certify tau >= THETA ----
        if (wid == 0) {
            const int n = s_n;
            float c0 = (lane < n)      ? s_cand[lane]      : NEG_INF;
            float c1 = (lane + 32 < n) ? s_cand[lane + 32] : NEG_INF;
            float s0 = (c0 > NEG_INF ? c0 : 0.0f) + (c1 > NEG_INF ? c1 : 0.0f);
            #pragma unroll
            for (int o = 16; o > 0; o >>= 1) s0 += __shfl_xor_sync(FULLM, s0, o);
            float tau = (s0 - 1.0f) / (float)(n > 0 ? (n <= CAP ? n : CAP) : 1);
            int prev = -1;
            #pragma unroll 1
            for (int it = 0; it < 32; it++) {
                float s = 0.0f, cnt = 0.0f;
                bool a0 = c0 > tau, a1 = c1 > tau;
                s += a0 ? c0 : 0.0f;  cnt += a0 ? 1.0f : 0.0f;
                s += a1 ? c1 : 0.0f;  cnt += a1 ? 1.0f : 0.0f;
                #pragma unroll
                for (int o = 16; o > 0; o >>= 1) {
                    s   += __shfl_xor_sync(FULLM, s, o);
                    cnt += __shfl_xor_sync(FULLM, cnt, o);
                }
                if (cnt == 0.0f) break;
                tau = (s - 1.0f) / cnt;
                int k = (int)cnt;
                if (k == prev) break;
                prev = k;
            }
            if (lane == 0) {
                s_tau = tau;
                s_ok  = (n > 0 && n <= CAP && tau >= THETA) ? 1 : 0;
                s_n   = 0;   // next gather begins only after the next barrier
            }
        }
        __syncthreads();   // s_tau/s_ok visible, s_n reset

        if (s_ok) {
            // ---- fast path: coalesced streaming projection store ----
            const float tau = s_tau;
            #pragma unroll
            for (int j = 0; j < NF4; j++) {
                const float4 q = cur[j];
                float4 o;
                o.x = fmaxf(q.x - tau, 0.0f);
                o.y = fmaxf(q.y - tau, 0.0f);
                o.z = fmaxf(q.z - tau, 0.0f);
                o.w = fmaxf(q.w - tau, 0.0f);
                __stcs(&out4[r * F4PROW + tid + THREADS * j], o);
            }
        } else {
            // ---- fallback: full-block Michelot over register-resident row ----
            float tau;
            {
                float s = 0.0f;
                #pragma unroll
                for (int j = 0; j < NF4; j++)
                    s += (cur[j].x + cur[j].y) + (cur[j].z + cur[j].w);
                #pragma unroll
                for (int o = 16; o > 0; o >>= 1) s += __shfl_xor_sync(FULLM, s, o);
                if (lane == 0) s_red[wid] = s;
                __syncthreads();
                if (tid == 0) {
                    float tot = 0.0f;
                    #pragma unroll
                    for (int w = 0; w < NWARP; w++) tot += s_red[w];
                    s_tau = (tot - 1.0f) * (1.0f / (float)ROWLEN);
                }
                __syncthreads();
                tau = s_tau;
            }
            int k_prev = ROWLEN;
            #pragma unroll 1
            for (int it = 0; it < 64; it++) {
                float s = 0.0f, cf = 0.0f;
                #pragma unroll
                for (int j = 0; j < NF4; j++) {
                    const float4 q = cur[j];
                    if (q.x > tau) { s += q.x; cf += 1.0f; }
                    if (q.y > tau) { s += q.y; cf += 1.0f; }
                    if (q.z > tau) { s += q.z; cf += 1.0f; }
                    if (q.w > tau) { s += q.w; cf += 1.0f; }
                }
                #pragma unroll
                for (int o = 16; o > 0; o >>= 1) {
                    s  += __shfl_xor_sync(FULLM, s, o);
                    cf += __shfl_xor_sync(FULLM, cf, o);
                }
                if (lane == 0) { s_red[wid] = s; s_cnt[wid] = cf; }
                __syncthreads();
                if (tid == 0) {
                    float ts = 0.0f, tc = 0.0f;
                    #pragma unroll
                    for (int w = 0; w < NWARP; w++) { ts += s_red[w]; tc += s_cnt[w]; }
                    s_tau = (ts - 1.0f) / tc;
                    s_cnt[0] = tc;
                }
                __syncthreads();
                tau = s_tau;
                int k = (int)s_cnt[0];
                __syncthreads();
                if (k == k_prev) break;
                k_prev = k;
            }
            #pragma unroll
            for (int j = 0; j < NF4; j++) {
                const float4 q = cur[j];
                float4 o;
                o.x = fmaxf(q.x - tau, 0.0f);
                o.y = fmaxf(q.y - tau, 0.0f);
                o.z = fmaxf(q.z - tau, 0.0f);
                o.w = fmaxf(q.w - tau, 0.0f);
                out4[r * F4PROW + tid + THREADS * j] = o;
            }
        }

        if (rn >= rows) break;
        r = rn;
        #pragma unroll
        for (int j = 0; j < NF4; j++) cur[j] = nxt[j];
    }
}

extern "C" void kernel_launch(void* const* d_in, const int* in_sizes, int n_in,
                              void* d_out, int out_size) {
    const float* z = (const float*)d_in[0];
    float* out = (float*)d_out;
    int rows = in_sizes[0] / ROWLEN;
    int grid = GRID_CTAS < rows ? GRID_CTAS : rows;
    sparsemax_kernel<<<grid, THREADS>>>(z, out, rows);
}

// round 14
// speedup vs baseline: 1.1444x; 1.0386x over previous
#include <cuda_runtime.h>
#include <cuda_bf16.h>

// Sparsemax rows of 2048 fp32 — persistent CTA-per-row, split register prefetch.
// 128 threads/CTA, 16 elements (4 float4) per thread, 10 CTAs/SM.
// Prefetch of the next row is SPLIT to cap register liveness at 6 float4:
//   - slots 0,1 prefetched before the solve barriers (deep MLP window)
//   - slots 2,3 loaded right after their stores (covered by 10 CTAs/SM)
// Algorithm (proven): static THETA gather via max-prefiltered shared atomics;
// warp 0 Michelot on candidates; tau >= THETA self-certifies exactness (KKT);
// coalesced streaming store; full-block Michelot fallback for correctness.

#define ROWLEN  2048
#define THREADS 128
#define NF4     4                    // float4 per thread per row
#define NWARP   (THREADS / 32)       // 4
#define F4PROW  (ROWLEN / 4)         // 512
#define CAP     64
#define THETA   2.25f
#define NEG_INF (-3.0e38f)
#define FULLM   0xffffffffu
#define OCC     10
#define GRID_CTAS (148 * OCC)

__global__ __launch_bounds__(THREADS, OCC)
void sparsemax_kernel(const float* __restrict__ z, float* __restrict__ out, int rows) {
    const float4* __restrict__ z4   = reinterpret_cast<const float4*>(z);
    float4* __restrict__       out4 = reinterpret_cast<float4*>(out);
    const int tid  = threadIdx.x;
    const int lane = tid & 31;
    const int wid  = tid >> 5;
    const long long stride = gridDim.x;

    __shared__ float s_cand[CAP];
    __shared__ int   s_n;
    __shared__ float s_tau;
    __shared__ int   s_ok;
    __shared__ float s_red[NWARP];
    __shared__ float s_cnt[NWARP];

    long long r = blockIdx.x;
    if (r >= rows) return;

    if (tid == 0) s_n = 0;

    // prime: full first row (4 independent LDG.128)
    float4 cur[NF4];
    #pragma unroll
    for (int j = 0; j < NF4; j++)
        cur[j] = __ldcs(&z4[r * F4PROW + tid + THREADS * j]);
    __syncthreads();   // s_n init visible

    #pragma unroll 1
    while (true) {
        const long long rn = r + stride;
        const bool have_next = (rn < rows);

        // ---- gather candidates > THETA (per-quad max prefilter, rare atomics) ----
        // order: slots 2,3 first (they were loaded latest), 0,1 after
        #pragma unroll
        for (int jj = 0; jj < NF4; jj++) {
            const int j = (jj + 2) & 3;
            const float4 q = cur[j];
            float m = fmaxf(fmaxf(q.x, q.y), fmaxf(q.z, q.w));
            if (m > THETA) {
                if (q.x > THETA) { int ix = atomicAdd(&s_n, 1); if (ix < CAP) s_cand[ix] = q.x; }
                if (q.y > THETA) { int ix = atomicAdd(&s_n, 1); if (ix < CAP) s_cand[ix] = q.y; }
                if (q.z > THETA) { int ix = atomicAdd(&s_n, 1); if (ix < CAP) s_cand[ix] = q.z; }
                if (q.w > THETA) { int ix = atomicAdd(&s_n, 1); if (ix < CAP) s_cand[ix] = q.w; }
            }
        }

        // ---- early prefetch: first half of next row (2 independent LDG.128) ----
        float4 pre0, pre1;
        if (have_next) {
            pre0 = __ldcs(&z4[rn * F4PROW + tid]);
            pre1 = __ldcs(&z4[rn * F4PROW + tid + THREADS]);
        }
        __syncthreads();   // gather complete

        // ---- warp 0: Michelot on candidate set; certify tau >= THETA ----
        if (wid == 0) {
            const int n = s_n;
            float c0 = (lane < n)      ? s_cand[lane]      : NEG_INF;
            float c1 = (lane + 32 < n) ? s_cand[lane + 32] : NEG_INF;
            float s0 = (c0 > NEG_INF ? c0 : 0.0f) + (c1 > NEG_INF ? c1 : 0.0f);
            #pragma unroll
            for (int o = 16; o > 0; o >>= 1) s0 += __shfl_xor_sync(FULLM, s0, o);
            float tau = (s0 - 1.0f) / (float)(n > 0 ? (n <= CAP ? n : CAP) : 1);
            int prev = -1;
            #pragma unroll 1
            for (int it = 0; it < 32; it++) {
                float s = 0.0f, cnt = 0.0f;
                bool a0 = c0 > tau, a1 = c1 > tau;
                s += a0 ? c0 : 0.0f;  cnt += a0 ? 1.0f : 0.0f;
                s += a1 ? c1 : 0.0f;  cnt += a1 ? 1.0f : 0.0f;
                #pragma unroll
                for (int o = 16; o > 0; o >>= 1) {
                    s   += __shfl_xor_sync(FULLM, s, o);
                    cnt += __shfl_xor_sync(FULLM, cnt, o);
                }
                if (cnt == 0.0f) break;
                tau = (s - 1.0f) / cnt;
                int k = (int)cnt;
                if (k == prev) break;
                prev = k;
            }
            if (lane == 0) {
                s_tau = tau;
                s_ok  = (n > 0 && n <= CAP && tau >= THETA) ? 1 : 0;
                s_n   = 0;   // next gather begins only after the next barrier
            }
        }
        __syncthreads();   // s_tau/s_ok visible, s_n reset

        if (s_ok) {
            const float tau = s_tau;
            // stores for slots 2,3 first, then immediately reload them with
            // the next row's second half (consumed first next iteration)
            #pragma unroll
            for (int j = 2; j < NF4; j++) {
                const float4 q = cur[j];
                float4 o;
                o.x = fmaxf(q.x - tau, 0.0f);
                o.y = fmaxf(q.y - tau, 0.0f);
                o.z = fmaxf(q.z - tau, 0.0f);
                o.w = fmaxf(q.w - tau, 0.0f);
                __stcs(&out4[r * F4PROW + tid + THREADS * j], o);
            }
            if (have_next) {
                cur[2] = __ldcs(&z4[rn * F4PROW + tid + THREADS * 2]);
                cur[3] = __ldcs(&z4[rn * F4PROW + tid + THREADS * 3]);
            }
            #pragma unroll
            for (int j = 0; j < 2; j++) {
                const float4 q = cur[j];
                float4 o;
                o.x = fmaxf(q.x - tau, 0.0f);
                o.y = fmaxf(q.y - tau, 0.0f);
                o.z = fmaxf(q.z - tau, 0.0f);
                o.w = fmaxf(q.w - tau, 0.0f);
                __stcs(&out4[r * F4PROW + tid + THREADS * j], o);
            }
        } else {
            // ---- fallback: full-block Michelot over register-resident row ----
            float tau;
            {
                float s = 0.0f;
                #pragma unroll
                for (int j = 0; j < NF4; j++)
                    s += (cur[j].x + cur[j].y) + (cur[j].z + cur[j].w);
                #pragma unroll
                for (int o = 16; o > 0; o >>= 1) s += __shfl_xor_sync(FULLM, s, o);
                if (lane == 0) s_red[wid] = s;
                __syncthreads();
                if (tid == 0) {
                    float tot = 0.0f;
                    #pragma unroll
                    for (int w = 0; w < NWARP; w++) tot += s_red[w];
                    s_tau = (tot - 1.0f) * (1.0f / (float)ROWLEN);
                }
                __syncthreads();
                tau = s_tau;
            }
            int k_prev = ROWLEN;
            #pragma unroll 1
            for (int it = 0; it < 64; it++) {
                float s = 0.0f, cf = 0.0f;
                #pragma unroll
                for (int j = 0; j < NF4; j++) {
                    const float4 q = cur[j];
                    if (q.x > tau) { s += q.x; cf += 1.0f; }
                    if (q.y > tau) { s += q.y; cf += 1.0f; }
                    if (q.z > tau) { s += q.z; cf += 1.0f; }
                    if (q.w > tau) { s += q.w; cf += 1.0f; }
                }
                #pragma unroll
                for (int o = 16; o > 0; o >>= 1) {
                    s  += __shfl_xor_sync(FULLM, s, o);
                    cf += __shfl_xor_sync(FULLM, cf, o);
                }
                if (lane == 0) { s_red[wid] = s; s_cnt[wid] = cf; }
                __syncthreads();
                if (tid == 0) {
                    float ts = 0.0f, tc = 0.0f;
                    #pragma unroll
                    for (int w = 0; w < NWARP; w++) { ts += s_red[w]; tc += s_cnt[w]; }
                    s_tau = (ts - 1.0f) / tc;
                    s_cnt[0] = tc;
                }
                __syncthreads();
                tau = s_tau;
                int k = (int)s_cnt[0];
                __syncthreads();
                if (k == k_prev) break;
                k_prev = k;
            }
            #pragma unroll
            for (int j = 0; j < NF4; j++) {
                const float4 q = cur[j];
                float4 o;
                o.x = fmaxf(q.x - tau, 0.0f);
                o.y = fmaxf(q.y - tau, 0.0f);
                o.z = fmaxf(q.z - tau, 0.0f);
                o.w = fmaxf(q.w - tau, 0.0f);
                out4[r * F4PROW + tid + THREADS * j] = o;
            }
            if (have_next) {
                cur[2] = __ldcs(&z4[rn * F4PROW + tid + THREADS * 2]);
                cur[3] = __ldcs(&z4[rn * F4PROW + tid + THREADS * 3]);
            }
        }

        if (!have_next) break;
        r = rn;
        cur[0] = pre0;
        cur[1] = pre1;
    }
}

extern "C" void kernel_launch(void* const* d_in, const int* in_sizes, int n_in,
                              void* d_out, int out_size) {
    const float* z = (const float*)d_in[0];
    float* out = (float*)d_out;
    int rows = in_sizes[0] / ROWLEN;
    int grid = GRID_CTAS < rows ? GRID_CTAS : rows;
    sparsemax_kernel<<<grid, THREADS>>>(z, out, rows);
}